// round 12
// baseline (speedup 1.0000x reference)
#include <cuda_runtime.h>
#include <cuda_bf16.h>

#define LLEN 1024
#define DD   128
#define EPSF 1e-5f
#define LP   2
#define NTILE 1024    // 512 l-tiles (2 l each) x 2 d-halves
#define BUFB 25600    // bytes per round buffer: A 16*1056 + B 16*544
#define NRP  16       // R partials (m-groups of 64)

// ---------------- scratch (device globals; no allocation) ----------------
__device__ float    g_a  [LLEN * DD];
__device__ float    g_tx [LLEN * DD];
__device__ float    g_Rp [NRP * LLEN * DD];
__device__ float    g_o1 [LLEN * DD];
__device__ __align__(16) unsigned g_ahm[512 * 256];   // [kp][c][{hi,mid}]
__device__ __align__(16) unsigned g_bhm[512 * 256];   // [kp][d][{hi,mid}]
__device__ unsigned g_mkp[LLEN * 512];
__device__ unsigned g_tile_ctr;

// ---------------- helpers ----------------
__device__ __forceinline__ unsigned smem_u32(const void* p) {
    unsigned a;
    asm("{ .reg .u64 t; cvta.to.shared.u64 t, %1; cvt.u32.u64 %0, t; }" : "=r"(a) : "l"(p));
    return a;
}
// L1-allocating async copy: operands stay L1-resident across tiles.
#define CP_ASYNC16(dst, src) \
    asm volatile("cp.async.ca.shared.global [%0], [%1], 16;" :: "r"(dst), "l"(src))
#define CP_COMMIT() asm volatile("cp.async.commit_group;" ::: "memory")
#define CP_WAIT0()  asm volatile("cp.async.wait_group 0;" ::: "memory")

__device__ __forceinline__ unsigned pack_bf16x2(float lo, float hi) {
    unsigned u;
    asm("cvt.rn.bf16x2.f32 %0, %1, %2;" : "=r"(u) : "f"(hi), "f"(lo));
    return u;
}
__device__ __forceinline__ void split_bf16(float x0, float x1, unsigned& uh, unsigned& um) {
    uh = pack_bf16x2(x0, x1);
    float h0 = __uint_as_float(uh << 16);
    float h1 = __uint_as_float(uh & 0xFFFF0000u);
    um = pack_bf16x2(x0 - h0, x1 - h1);
}
__device__ __forceinline__ void mma_bf16(float* c, unsigned a0, unsigned a1, unsigned a2,
                                         unsigned a3, unsigned b0, unsigned b1) {
    asm volatile(
        "mma.sync.aligned.m16n8k16.row.col.f32.bf16.bf16.f32 "
        "{%0,%1,%2,%3}, {%4,%5,%6,%7}, {%8,%9}, {%0,%1,%2,%3};"
        : "+f"(c[0]), "+f"(c[1]), "+f"(c[2]), "+f"(c[3])
        : "r"(a0), "r"(a1), "r"(a2), "r"(a3), "r"(b0), "r"(b1));
}
__device__ __forceinline__ unsigned u64lo(unsigned long long v) { return (unsigned)v; }
__device__ __forceinline__ unsigned u64hi(unsigned long long v) { return (unsigned)(v >> 32); }

// ---------------- kernel 1: projections + fused interleaved bf16 split ----------------
__global__ __launch_bounds__(256) void proj_kernel(
    const float* __restrict__ x,
    const float* __restrict__ Wl,  const float* __restrict__ bl,
    const float* __restrict__ Wl2, const float* __restrict__ bl2)
{
    __shared__ float xs[8 * DD];
    __shared__ float ws[32 * 129];
    __shared__ float ys[8 * DD];
    const int t = threadIdx.x, l0 = blockIdx.x * 8;
    const int mat = blockIdx.y;
    const int dloc = t & 31, lrow = t >> 5;
    for (int i = t; i < 8 * DD; i += 256) xs[i] = x[l0 * DD + i];

    const float* W    = mat ? Wl2 : Wl;
    const float* bias = mat ? bl2 : bl;
    float*       outp = mat ? g_tx : g_a;
    unsigned long long* ohm = (unsigned long long*)(mat ? g_bhm : g_ahm);
    for (int dc = 0; dc < 4; dc++) {
        const int d0 = dc * 32;
        __syncthreads();
        for (int i = t; i < 32 * DD; i += 256) {
            int r = i >> 7, c = i & 127;
            ws[r * 129 + c] = W[(d0 + r) * DD + c];
        }
        __syncthreads();
        float acc = 0.f;
        #pragma unroll 8
        for (int c = 0; c < DD; c++) acc += xs[lrow * DD + c] * ws[dloc * 129 + c];
        acc += bias[d0 + dloc];
        outp[(l0 + lrow) * DD + d0 + dloc] = acc;
        ys[lrow * DD + d0 + dloc] = acc;
    }
    __syncthreads();
    #pragma unroll
    for (int i = 0; i < 2; i++) {
        int idx = t + 256 * i;
        int j = idx >> 7, c = idx & 127;
        float x0 = ys[(2 * j) * DD + c];
        float x1 = ys[(2 * j + 1) * DD + c];
        unsigned uh, um; split_bf16(x0, x1, uh, um);
        int kp = (l0 >> 1) + j;
        ohm[kp * 128 + c] = (unsigned long long)uh | ((unsigned long long)um << 32);
    }
}

// ---------------- kernel 2: mask pair-words + tile counter reset ----------------
__global__ __launch_bounds__(256) void prep_mask_kernel(const int* __restrict__ mask)
{
    const int idx = blockIdx.x * 256 + threadIdx.x;
    if (idx == 0) g_tile_ctr = 0u;
    const int l = idx >> 9, kp = idx & 511;
    int ma = mask[l * LLEN + 2 * kp];
    int mb = mask[l * LLEN + 2 * kp + 1];
    g_mkp[idx] = (ma ? 0x0000FFFFu : 0u) | (mb ? 0xFFFF0000u : 0u);
}

// ---------------- kernel 3: R partials (16 m-groups of 64) ----------------
__global__ __launch_bounds__(256) void r_kernel(const int* __restrict__ mask)
{
    __shared__ float s_txc[64 * DD];
    __shared__ float s_mk [16 * 64];
    const int t = threadIdx.x;
    const int l0 = blockIdx.x * 16;
    const int mg = blockIdx.y;
    const int m0 = mg * 64;
    const int d4 = t & 31, lg = t >> 5;

    #pragma unroll
    for (int r = 0; r < 8; r++) {
        int idx = t + 256 * r;
        int rw = idx >> 5, c4 = idx & 31;
        *(float4*)&s_txc[rw * DD + c4 * 4] = *(const float4*)&g_tx[(m0 + rw) * DD + c4 * 4];
    }
    #pragma unroll
    for (int r = 0; r < 4; r++) {
        int idx = t + 256 * r;
        int li = idx >> 6, mm = idx & 63;
        s_mk[li * 64 + mm] = (mask[(l0 + li) * LLEN + m0 + mm] != 0) ? 1.f : 0.f;
    }
    __syncthreads();

    float4 a0 = {0.f,0.f,0.f,0.f}, a1 = {0.f,0.f,0.f,0.f};
    #pragma unroll 4
    for (int mm = 0; mm < 64; mm++) {
        float4 tv = *(float4*)&s_txc[mm * DD + d4 * 4];
        float f0 = s_mk[(lg * 2) * 64 + mm];
        float f1 = s_mk[(lg * 2 + 1) * 64 + mm];
        a0.x += tv.x * f0; a0.y += tv.y * f0; a0.z += tv.z * f0; a0.w += tv.w * f0;
        a1.x += tv.x * f1; a1.y += tv.y * f1; a1.z += tv.z * f1; a1.w += tv.w * f1;
    }
    *(float4*)&g_Rp[(mg * LLEN + l0 + lg * 2) * DD + d4 * 4]     = a0;
    *(float4*)&g_Rp[(mg * LLEN + l0 + lg * 2 + 1) * DD + d4 * 4] = a1;
}

// ---------------- kernel 4: persistent GEMM, LDS.64 pair operands, 2 CTAs/SM ----------------
// SMEM/CTA: s_a @0 (1024), s_mk @1024 (4096),
//   buf0 @5120, buf1 @30720; each: A 16x1056B (row stride 264 words) then B 16x544B
//   (row stride 136 words) = 25600 -> end 56320.
// Epilogue reuse: wlo @5120 (33792), ep @38912 (4096). Dynamic = 56320.
__global__ __launch_bounds__(256, 2) void cop_kernel(const float* __restrict__ Wlo)
{
    extern __shared__ char sm[];
    float*    s_a   = (float*)sm;
    unsigned* s_mk  = (unsigned*)(sm + 1024);
    float*    s_wlo = (float*)(sm + 5120);
    float*    s_ep  = (float*)(sm + 38912);
    __shared__ int s_tile;
    const unsigned sb = smem_u32(sm);

    const int t    = threadIdx.x;
    const int w    = t >> 5;
    const int lane = t & 31;
    const int gid  = lane >> 2;
    const int tig  = lane & 3;
    const int ct0  = w * 16;

    for (;;) {
        if (t == 0) s_tile = (int)atomicAdd(&g_tile_ctr, 1u);
        __syncthreads();
        const int tile = s_tile;
        if (tile >= NTILE) break;
        const int l0 = (tile >> 1) * LP;
        const int d0 = (tile & 1) * 64;

        s_a[t] = g_a[(l0 + (t >> 7)) * DD + (t & 127)];
        #pragma unroll
        for (int i = 0; i < 4; i++) {
            int idx = t + 256 * i;
            s_mk[idx] = g_mkp[(l0 + (idx >> 9)) * 512 + (idx & 511)];
        }

        float acc[LP][8][4];
        #pragma unroll
        for (int l = 0; l < LP; l++)
            #pragma unroll
            for (int dg = 0; dg < 8; dg++)
                #pragma unroll
                for (int q = 0; q < 4; q++) acc[l][dg][q] = 0.f;

        // ---- issue round-0 copies ----
        {
            const unsigned bufu = sb + 5120;
            #pragma unroll
            for (int i = 0; i < 4; i++) {       // A: 1024 chunks
                int idx = t + 256 * i;
                int rw = idx >> 6, ch = idx & 63;
                CP_ASYNC16(bufu + rw * 1056 + ch * 16,
                           (const char*)g_ahm + rw * 1024 + ch * 16);
            }
            #pragma unroll
            for (int i = 0; i < 2; i++) {       // B: 512 chunks
                int idx = t + 256 * i;
                int rw = idx >> 5, ch = idx & 31;
                CP_ASYNC16(bufu + 16896 + rw * 544 + ch * 16,
                           (const char*)g_bhm + rw * 1024 + d0 * 8 + ch * 16);
            }
            CP_COMMIT();
        }

        #pragma unroll 1
        for (int r = 0; r < 32; r++) {
            CP_WAIT0();
            __syncthreads();
            if (r < 31) {
                const int kg = (r + 1) * 16;
                const unsigned bufu = sb + 5120 + ((r + 1) & 1) * BUFB;
                #pragma unroll
                for (int i = 0; i < 4; i++) {
                    int idx = t + 256 * i;
                    int rw = idx >> 6, ch = idx & 63;
                    CP_ASYNC16(bufu + rw * 1056 + ch * 16,
                               (const char*)g_ahm + (kg + rw) * 1024 + ch * 16);
                }
                #pragma unroll
                for (int i = 0; i < 2; i++) {
                    int idx = t + 256 * i;
                    int rw = idx >> 5, ch = idx & 31;
                    CP_ASYNC16(bufu + 16896 + rw * 544 + ch * 16,
                               (const char*)g_bhm + (kg + rw) * 1024 + d0 * 8 + ch * 16);
                }
                CP_COMMIT();
            }
            char* buf = sm + 5120 + (r & 1) * BUFB;
            unsigned* sA = (unsigned*)(buf);             // [16][264] words (pairs)
            unsigned* sB = (unsigned*)(buf + 16896);     // [16][136] words (pairs)
            const int kpg = r * 16;
            #pragma unroll
            for (int s = 0; s < 2; s++) {
                const int kb = 8 * s;
                const int ra = (kb + tig) * 264 + (ct0 + gid) * 2;
                const int rb = (kb + tig + 4) * 264 + (ct0 + gid) * 2;
                unsigned long long A0 = *(unsigned long long*)&sA[ra];
                unsigned long long A1 = *(unsigned long long*)&sA[ra + 16];
                unsigned long long A2 = *(unsigned long long*)&sA[rb];
                unsigned long long A3 = *(unsigned long long*)&sA[rb + 16];
                unsigned xh[LP][4], xm[LP][4];
                #pragma unroll
                for (int l = 0; l < LP; l++) {
                    const unsigned mkl = s_mk[l * 512 + kpg + kb + tig];
                    const unsigned mkh = s_mk[l * 512 + kpg + kb + tig + 4];
                    xh[l][0] = u64lo(A0) & mkl; xh[l][1] = u64lo(A1) & mkl;
                    xh[l][2] = u64lo(A2) & mkh; xh[l][3] = u64lo(A3) & mkh;
                    xm[l][0] = u64hi(A0) & mkl; xm[l][1] = u64hi(A1) & mkl;
                    xm[l][2] = u64hi(A2) & mkh; xm[l][3] = u64hi(A3) & mkh;
                }
                #pragma unroll
                for (int h = 0; h < 2; h++) {
                    const int bb0 = (kb + tig) * 136 + (h * 32 + gid) * 2;
                    const int bb1 = (kb + tig + 4) * 136 + (h * 32 + gid) * 2;
                    unsigned long long B0[4], B1[4];
                    #pragma unroll
                    for (int p = 0; p < 4; p++) {
                        B0[p] = *(unsigned long long*)&sB[bb0 + p * 16];
                        B1[p] = *(unsigned long long*)&sB[bb1 + p * 16];
                    }
                    #pragma unroll
                    for (int l = 0; l < LP; l++)      // hh
                        #pragma unroll
                        for (int p = 0; p < 4; p++)
                            mma_bf16(acc[l][h * 4 + p], xh[l][0], xh[l][1], xh[l][2], xh[l][3],
                                     u64lo(B0[p]), u64lo(B1[p]));
                    #pragma unroll
                    for (int l = 0; l < LP; l++)      // mh
                        #pragma unroll
                        for (int p = 0; p < 4; p++)
                            mma_bf16(acc[l][h * 4 + p], xm[l][0], xm[l][1], xm[l][2], xm[l][3],
                                     u64lo(B0[p]), u64lo(B1[p]));
                    #pragma unroll
                    for (int l = 0; l < LP; l++)      // hm
                        #pragma unroll
                        for (int p = 0; p < 4; p++)
                            mma_bf16(acc[l][h * 4 + p], xh[l][0], xh[l][1], xh[l][2], xh[l][3],
                                     u64hi(B0[p]), u64hi(B1[p]));
                }
            }
        }

        // ---- epilogue: sum_c a_l[c]*Wlo[d,c]*H ----
        __syncthreads();
        #pragma unroll
        for (int i = 0; i < 8; i++) {
            int idx = t + 256 * i;
            int dd = idx >> 5, c4 = idx & 31;
            *(float4*)&s_wlo[dd * 132 + c4 * 4] = *(const float4*)&Wlo[(d0 + dd) * DD + c4 * 4];
        }
        __syncthreads();

        const int cA = ct0 + gid, cB = cA + 8;
        #pragma unroll
        for (int l = 0; l < LP; l++) {
            const float aA = s_a[l * DD + cA];
            const float aB = s_a[l * DD + cB];
            float pd[16];
            #pragma unroll
            for (int dg = 0; dg < 8; dg++) {
                const int dl0 = dg * 8 + 2 * tig;
                float w0  = s_wlo[dl0 * 132 + cA],  w1  = s_wlo[(dl0 + 1) * 132 + cA];
                float w0b = s_wlo[dl0 * 132 + cB],  w1b = s_wlo[(dl0 + 1) * 132 + cB];
                pd[2 * dg]     = acc[l][dg][0] * (aA * w0) + acc[l][dg][2] * (aB * w0b);
                pd[2 * dg + 1] = acc[l][dg][1] * (aA * w1) + acc[l][dg][3] * (aB * w1b);
            }
            #pragma unroll
            for (int off = 16; off >= 4; off >>= 1)
                #pragma unroll
                for (int q = 0; q < 16; q++)
                    pd[q] += __shfl_down_sync(0xffffffffu, pd[q], off);
            if (lane < 4) {
                #pragma unroll
                for (int dg = 0; dg < 8; dg++) {
                    s_ep[w * 128 + l * 64 + dg * 8 + 2 * lane]     = pd[2 * dg];
                    s_ep[w * 128 + l * 64 + dg * 8 + 2 * lane + 1] = pd[2 * dg + 1];
                }
            }
        }
        __syncthreads();
        if (t < 128) {
            const int l = t >> 6, dloc = t & 63;
            float v = s_ep[t] + s_ep[128 + t] + s_ep[256 + t] + s_ep[384 + t]
                    + s_ep[512 + t] + s_ep[640 + t] + s_ep[768 + t] + s_ep[896 + t];
            g_o1[(l0 + l) * DD + d0 + dloc] = v;
        }
    }
}

// ---------------- kernel 5: residual + blo*R + LayerNorm ----------------
__global__ __launch_bounds__(128) void ln_kernel(
    const float* __restrict__ x,   const float* __restrict__ blo,
    const float* __restrict__ gamma, const float* __restrict__ beta,
    float* __restrict__ out)
{
    __shared__ float w1[4], w2[4];
    __shared__ float mu_s, rstd_s;
    const int l = blockIdx.x;
    const int d = threadIdx.x;
    float Rv = 0.f;
    #pragma unroll
    for (int p = 0; p < NRP; p++) Rv += g_Rp[(p * LLEN + l) * DD + d];
    float y = x[l * DD + d] + g_o1[l * DD + d] + blo[d] * Rv;
    float s1 = y, s2 = y * y;
    #pragma unroll
    for (int off = 16; off > 0; off >>= 1) {
        s1 += __shfl_down_sync(0xffffffffu, s1, off);
        s2 += __shfl_down_sync(0xffffffffu, s2, off);
    }
    const int wid = d >> 5, lid = d & 31;
    if (lid == 0) { w1[wid] = s1; w2[wid] = s2; }
    __syncthreads();
    if (d == 0) {
        float t1 = w1[0] + w1[1] + w1[2] + w1[3];
        float t2 = w2[0] + w2[1] + w2[2] + w2[3];
        float mu = t1 * (1.f / DD);
        float var = t2 * (1.f / DD) - mu * mu;
        mu_s = mu; rstd_s = rsqrtf(var + EPSF);
    }
    __syncthreads();
    out[l * DD + d] = (y - mu_s) * rstd_s * gamma[d] + beta[d];
}

// ---------------- launch (cop 4th so ncu profiles it) ----------------
extern "C" void kernel_launch(void* const* d_in, const int* in_sizes, int n_in,
                              void* d_out, int out_size)
{
    (void)in_sizes; (void)n_in; (void)out_size;
    const float* x     = (const float*)d_in[0];
    const int*   mask  = (const int*)  d_in[1];
    const float* Wl    = (const float*)d_in[2];
    const float* bl    = (const float*)d_in[3];
    const float* Wlo   = (const float*)d_in[4];
    const float* blo   = (const float*)d_in[5];
    const float* Wl2   = (const float*)d_in[6];
    const float* bl2   = (const float*)d_in[7];
    const float* gamma = (const float*)d_in[8];
    const float* beta  = (const float*)d_in[9];
    float* out = (float*)d_out;

    static int smem_set = 0;
    if (!smem_set) {
        cudaFuncSetAttribute(cop_kernel, cudaFuncAttributeMaxDynamicSharedMemorySize, 56320);
        smem_set = 1;
    }

    proj_kernel<<<dim3(128, 2), 256>>>(x, Wl, bl, Wl2, bl2);   // 1
    prep_mask_kernel<<<2048, 256>>>(mask);                     // 2
    r_kernel<<<dim3(64, 16), 256>>>(mask);                     // 3
    cop_kernel<<<296, 256, 56320>>>(Wlo);                      // 4
    ln_kernel<<<1024, 128>>>(x, blo, gamma, beta, out);        // 5
}

// round 13
// speedup vs baseline: 1.1485x; 1.1485x over previous
#include <cuda_runtime.h>
#include <cuda_bf16.h>

#define LLEN 1024
#define DD   128
#define EPSF 1e-5f
#define LP   2
#define NTILE 1024    // 512 l-tiles (2 l each) x 2 d-halves
#define BUFB 26624    // bytes per round buffer: Ah 8704 + Am 8704 + Bh 4608 + Bm 4608
#define NRP  16       // R partials (m-groups of 64)

// ---------------- scratch (device globals; no allocation) ----------------
__device__ float    g_a  [LLEN * DD];
__device__ float    g_tx [LLEN * DD];
__device__ float    g_Rp [NRP * LLEN * DD];
__device__ float    g_o1 [LLEN * DD];
__device__ unsigned g_ah [512 * DD];
__device__ unsigned g_am [512 * DD];
__device__ unsigned g_bh [512 * DD];
__device__ unsigned g_bm [512 * DD];
__device__ unsigned g_mkp[LLEN * 512];
__device__ unsigned g_tile_ctr;

// ---------------- helpers ----------------
__device__ __forceinline__ unsigned smem_u32(const void* p) {
    unsigned a;
    asm("{ .reg .u64 t; cvta.to.shared.u64 t, %1; cvt.u32.u64 %0, t; }" : "=r"(a) : "l"(p));
    return a;
}
// L1-allocating async copy: operands stay L1-resident across tiles.
#define CP_ASYNC16(dst, src) \
    asm volatile("cp.async.ca.shared.global [%0], [%1], 16;" :: "r"(dst), "l"(src))
#define CP_COMMIT() asm volatile("cp.async.commit_group;" ::: "memory")
#define CP_WAIT0()  asm volatile("cp.async.wait_group 0;" ::: "memory")

__device__ __forceinline__ unsigned pack_bf16x2(float lo, float hi) {
    unsigned u;
    asm("cvt.rn.bf16x2.f32 %0, %1, %2;" : "=r"(u) : "f"(hi), "f"(lo));
    return u;
}
__device__ __forceinline__ void split_bf16(float x0, float x1, unsigned& uh, unsigned& um) {
    uh = pack_bf16x2(x0, x1);
    float h0 = __uint_as_float(uh << 16);
    float h1 = __uint_as_float(uh & 0xFFFF0000u);
    um = pack_bf16x2(x0 - h0, x1 - h1);
}
__device__ __forceinline__ void mma_bf16(float* c, unsigned a0, unsigned a1, unsigned a2,
                                         unsigned a3, unsigned b0, unsigned b1) {
    asm volatile(
        "mma.sync.aligned.m16n8k16.row.col.f32.bf16.bf16.f32 "
        "{%0,%1,%2,%3}, {%4,%5,%6,%7}, {%8,%9}, {%0,%1,%2,%3};"
        : "+f"(c[0]), "+f"(c[1]), "+f"(c[2]), "+f"(c[3])
        : "r"(a0), "r"(a1), "r"(a2), "r"(a3), "r"(b0), "r"(b1));
}

// ---------------- kernel 1: projections + fused bf16 split (one mat per CTA) ----------------
__global__ __launch_bounds__(256) void proj_kernel(
    const float* __restrict__ x,
    const float* __restrict__ Wl,  const float* __restrict__ bl,
    const float* __restrict__ Wl2, const float* __restrict__ bl2)
{
    __shared__ float xs[8 * DD];
    __shared__ float ws[32 * 129];
    __shared__ float ys[8 * DD];
    const int t = threadIdx.x, l0 = blockIdx.x * 8;
    const int mat = blockIdx.y;
    const int dloc = t & 31, lrow = t >> 5;
    for (int i = t; i < 8 * DD; i += 256) xs[i] = x[l0 * DD + i];

    const float* W    = mat ? Wl2 : Wl;
    const float* bias = mat ? bl2 : bl;
    float*       outp = mat ? g_tx : g_a;
    unsigned*    oh   = mat ? g_bh : g_ah;
    unsigned*    om   = mat ? g_bm : g_am;
    for (int dc = 0; dc < 4; dc++) {
        const int d0 = dc * 32;
        __syncthreads();
        for (int i = t; i < 32 * DD; i += 256) {
            int r = i >> 7, c = i & 127;
            ws[r * 129 + c] = W[(d0 + r) * DD + c];
        }
        __syncthreads();
        float acc = 0.f;
        #pragma unroll 8
        for (int c = 0; c < DD; c++) acc += xs[lrow * DD + c] * ws[dloc * 129 + c];
        acc += bias[d0 + dloc];
        outp[(l0 + lrow) * DD + d0 + dloc] = acc;
        ys[lrow * DD + d0 + dloc] = acc;
    }
    __syncthreads();
    #pragma unroll
    for (int i = 0; i < 2; i++) {
        int idx = t + 256 * i;
        int j = idx >> 7, c = idx & 127;
        float x0 = ys[(2 * j) * DD + c];
        float x1 = ys[(2 * j + 1) * DD + c];
        unsigned uh, um; split_bf16(x0, x1, uh, um);
        int kp = (l0 >> 1) + j;
        oh[kp * DD + c] = uh; om[kp * DD + c] = um;
    }
}

// ---------------- kernel 2: mask pair-words + tile counter reset ----------------
__global__ __launch_bounds__(256) void prep_mask_kernel(const int* __restrict__ mask)
{
    const int idx = blockIdx.x * 256 + threadIdx.x;
    if (idx == 0) g_tile_ctr = 0u;
    const int l = idx >> 9, kp = idx & 511;
    int ma = mask[l * LLEN + 2 * kp];
    int mb = mask[l * LLEN + 2 * kp + 1];
    g_mkp[idx] = (ma ? 0x0000FFFFu : 0u) | (mb ? 0xFFFF0000u : 0u);
}

// ---------------- kernel 3: R partials (16 m-groups of 64) ----------------
__global__ __launch_bounds__(256) void r_kernel(const int* __restrict__ mask)
{
    __shared__ float s_txc[64 * DD];
    __shared__ float s_mk [16 * 64];
    const int t = threadIdx.x;
    const int l0 = blockIdx.x * 16;
    const int mg = blockIdx.y;
    const int m0 = mg * 64;
    const int d4 = t & 31, lg = t >> 5;

    #pragma unroll
    for (int r = 0; r < 8; r++) {
        int idx = t + 256 * r;
        int rw = idx >> 5, c4 = idx & 31;
        *(float4*)&s_txc[rw * DD + c4 * 4] = *(const float4*)&g_tx[(m0 + rw) * DD + c4 * 4];
    }
    #pragma unroll
    for (int r = 0; r < 4; r++) {
        int idx = t + 256 * r;
        int li = idx >> 6, mm = idx & 63;
        s_mk[li * 64 + mm] = (mask[(l0 + li) * LLEN + m0 + mm] != 0) ? 1.f : 0.f;
    }
    __syncthreads();

    float4 a0 = {0.f,0.f,0.f,0.f}, a1 = {0.f,0.f,0.f,0.f};
    #pragma unroll 4
    for (int mm = 0; mm < 64; mm++) {
        float4 tv = *(float4*)&s_txc[mm * DD + d4 * 4];
        float f0 = s_mk[(lg * 2) * 64 + mm];
        float f1 = s_mk[(lg * 2 + 1) * 64 + mm];
        a0.x += tv.x * f0; a0.y += tv.y * f0; a0.z += tv.z * f0; a0.w += tv.w * f0;
        a1.x += tv.x * f1; a1.y += tv.y * f1; a1.z += tv.z * f1; a1.w += tv.w * f1;
    }
    *(float4*)&g_Rp[(mg * LLEN + l0 + lg * 2) * DD + d4 * 4]     = a0;
    *(float4*)&g_Rp[(mg * LLEN + l0 + lg * 2 + 1) * DD + d4 * 4] = a1;
}

// ---------------- kernel 4: persistent GEMM, 2 CTAs/SM, LP=2, KC=32, cp.async.ca ----------------
// (verified R10/R11 kernel, unchanged)
__global__ __launch_bounds__(256, 2) void cop_kernel(const float* __restrict__ Wlo)
{
    extern __shared__ char sm[];
    float*    s_a   = (float*)sm;
    unsigned* s_mk  = (unsigned*)(sm + 1024);
    float*    s_wlo = (float*)(sm + 5120);
    float*    s_ep  = (float*)(sm + 38912);
    __shared__ int s_tile;
    const unsigned sb = smem_u32(sm);

    const int t    = threadIdx.x;
    const int w    = t >> 5;
    const int lane = t & 31;
    const int gid  = lane >> 2;
    const int tig  = lane & 3;
    const int ct0  = w * 16;

    for (;;) {
        if (t == 0) s_tile = (int)atomicAdd(&g_tile_ctr, 1u);
        __syncthreads();
        const int tile = s_tile;
        if (tile >= NTILE) break;
        const int l0 = (tile >> 1) * LP;
        const int d0 = (tile & 1) * 64;

        if (t < LP * DD) s_a[t] = g_a[(l0 + (t >> 7)) * DD + (t & 127)];
        #pragma unroll
        for (int i = 0; i < 4; i++) {
            int idx = t + 256 * i;
            s_mk[idx] = g_mkp[(l0 + (idx >> 9)) * 512 + (idx & 511)];
        }

        float acc[LP][8][4];
        #pragma unroll
        for (int l = 0; l < LP; l++)
            #pragma unroll
            for (int dg = 0; dg < 8; dg++)
                #pragma unroll
                for (int q = 0; q < 4; q++) acc[l][dg][q] = 0.f;

        {
            const unsigned bufu = sb + 5120;
            #pragma unroll
            for (int i = 0; i < 2; i++) {
                int idx = t + 256 * i;
                int rw = idx >> 5, c4 = idx & 31;
                const unsigned dsto = (rw * 136 + c4 * 4) * 4;
                CP_ASYNC16(bufu + dsto,        (const char*)(g_ah + rw * 128 + c4 * 4));
                CP_ASYNC16(bufu + 8704 + dsto, (const char*)(g_am + rw * 128 + c4 * 4));
            }
            {
                int rw = t >> 4, c4 = t & 15;
                const unsigned dsto = (rw * 72 + c4 * 4) * 4;
                CP_ASYNC16(bufu + 17408 + dsto, (const char*)(g_bh + rw * 128 + d0 + c4 * 4));
                CP_ASYNC16(bufu + 22016 + dsto, (const char*)(g_bm + rw * 128 + d0 + c4 * 4));
            }
            CP_COMMIT();
        }

        #pragma unroll 1
        for (int r = 0; r < 32; r++) {
            CP_WAIT0();
            __syncthreads();
            if (r < 31) {
                const int kg = (r + 1) * 16;
                const unsigned bufu = sb + 5120 + ((r + 1) & 1) * BUFB;
                #pragma unroll
                for (int i = 0; i < 2; i++) {
                    int idx = t + 256 * i;
                    int rw = idx >> 5, c4 = idx & 31;
                    const unsigned dsto = (rw * 136 + c4 * 4) * 4;
                    const unsigned srco = (kg + rw) * 128 + c4 * 4;
                    CP_ASYNC16(bufu + dsto,        (const char*)(g_ah + srco));
                    CP_ASYNC16(bufu + 8704 + dsto, (const char*)(g_am + srco));
                }
                {
                    int rw = t >> 4, c4 = t & 15;
                    const unsigned dsto = (rw * 72 + c4 * 4) * 4;
                    const unsigned srco = (kg + rw) * 128 + d0 + c4 * 4;
                    CP_ASYNC16(bufu + 17408 + dsto, (const char*)(g_bh + srco));
                    CP_ASYNC16(bufu + 22016 + dsto, (const char*)(g_bm + srco));
                }
                CP_COMMIT();
            }
            char* buf = sm + 5120 + (r & 1) * BUFB;
            unsigned* sAh = (unsigned*)(buf);
            unsigned* sAm = (unsigned*)(buf + 8704);
            unsigned* sBh = (unsigned*)(buf + 17408);
            unsigned* sBm = (unsigned*)(buf + 22016);
            const int kpg = r * 16;
            #pragma unroll
            for (int s = 0; s < 2; s++) {
                const int kb = 8 * s;
                unsigned ah0 = sAh[(kb + tig) * 136 + ct0 + gid];
                unsigned ah1 = sAh[(kb + tig) * 136 + ct0 + gid + 8];
                unsigned ah2 = sAh[(kb + tig + 4) * 136 + ct0 + gid];
                unsigned ah3 = sAh[(kb + tig + 4) * 136 + ct0 + gid + 8];
                unsigned am0 = sAm[(kb + tig) * 136 + ct0 + gid];
                unsigned am1 = sAm[(kb + tig) * 136 + ct0 + gid + 8];
                unsigned am2 = sAm[(kb + tig + 4) * 136 + ct0 + gid];
                unsigned am3 = sAm[(kb + tig + 4) * 136 + ct0 + gid + 8];
                unsigned mkl[LP], mkh[LP];
                #pragma unroll
                for (int l = 0; l < LP; l++) {
                    mkl[l] = s_mk[l * 512 + kpg + kb + tig];
                    mkh[l] = s_mk[l * 512 + kpg + kb + tig + 4];
                }
                unsigned b0[8], b1[8];
                #pragma unroll
                for (int dg = 0; dg < 8; dg++) {
                    b0[dg] = sBh[(kb + tig) * 72 + dg * 8 + gid];
                    b1[dg] = sBh[(kb + tig + 4) * 72 + dg * 8 + gid];
                }
                #pragma unroll
                for (int l = 0; l < LP; l++) {      // hh
                    unsigned x0 = ah0 & mkl[l], x1 = ah1 & mkl[l];
                    unsigned x2 = ah2 & mkh[l], x3 = ah3 & mkh[l];
                    #pragma unroll
                    for (int dg = 0; dg < 8; dg++)
                        mma_bf16(acc[l][dg], x0, x1, x2, x3, b0[dg], b1[dg]);
                }
                #pragma unroll
                for (int l = 0; l < LP; l++) {      // mh
                    unsigned x0 = am0 & mkl[l], x1 = am1 & mkl[l];
                    unsigned x2 = am2 & mkh[l], x3 = am3 & mkh[l];
                    #pragma unroll
                    for (int dg = 0; dg < 8; dg++)
                        mma_bf16(acc[l][dg], x0, x1, x2, x3, b0[dg], b1[dg]);
                }
                #pragma unroll
                for (int dg = 0; dg < 8; dg++) {
                    b0[dg] = sBm[(kb + tig) * 72 + dg * 8 + gid];
                    b1[dg] = sBm[(kb + tig + 4) * 72 + dg * 8 + gid];
                }
                #pragma unroll
                for (int l = 0; l < LP; l++) {      // hm
                    unsigned x0 = ah0 & mkl[l], x1 = ah1 & mkl[l];
                    unsigned x2 = ah2 & mkh[l], x3 = ah3 & mkh[l];
                    #pragma unroll
                    for (int dg = 0; dg < 8; dg++)
                        mma_bf16(acc[l][dg], x0, x1, x2, x3, b0[dg], b1[dg]);
                }
            }
        }

        // ---- epilogue ----
        __syncthreads();
        #pragma unroll
        for (int i = 0; i < 8; i++) {
            int idx = t + 256 * i;
            int dd = idx >> 5, c4 = idx & 31;
            *(float4*)&s_wlo[dd * 132 + c4 * 4] = *(const float4*)&Wlo[(d0 + dd) * DD + c4 * 4];
        }
        __syncthreads();

        const int cA = ct0 + gid, cB = cA + 8;
        #pragma unroll
        for (int l = 0; l < LP; l++) {
            const float aA = s_a[l * DD + cA];
            const float aB = s_a[l * DD + cB];
            float pd[16];
            #pragma unroll
            for (int dg = 0; dg < 8; dg++) {
                const int dl0 = dg * 8 + 2 * tig;
                float w0  = s_wlo[dl0 * 132 + cA],  w1  = s_wlo[(dl0 + 1) * 132 + cA];
                float w0b = s_wlo[dl0 * 132 + cB],  w1b = s_wlo[(dl0 + 1) * 132 + cB];
                pd[2 * dg]     = acc[l][dg][0] * (aA * w0) + acc[l][dg][2] * (aB * w0b);
                pd[2 * dg + 1] = acc[l][dg][1] * (aA * w1) + acc[l][dg][3] * (aB * w1b);
            }
            #pragma unroll
            for (int off = 16; off >= 4; off >>= 1)
                #pragma unroll
                for (int q = 0; q < 16; q++)
                    pd[q] += __shfl_down_sync(0xffffffffu, pd[q], off);
            if (lane < 4) {
                #pragma unroll
                for (int dg = 0; dg < 8; dg++) {
                    s_ep[w * 128 + l * 64 + dg * 8 + 2 * lane]     = pd[2 * dg];
                    s_ep[w * 128 + l * 64 + dg * 8 + 2 * lane + 1] = pd[2 * dg + 1];
                }
            }
        }
        __syncthreads();
        if (t < 128) {
            const int l = t >> 6, dloc = t & 63;
            float v = s_ep[t] + s_ep[128 + t] + s_ep[256 + t] + s_ep[384 + t]
                    + s_ep[512 + t] + s_ep[640 + t] + s_ep[768 + t] + s_ep[896 + t];
            g_o1[(l0 + l) * DD + d0 + dloc] = v;
        }
    }
}

// ---------------- kernel 5: residual + blo*R + LayerNorm ----------------
__global__ __launch_bounds__(128) void ln_kernel(
    const float* __restrict__ x,   const float* __restrict__ blo,
    const float* __restrict__ gamma, const float* __restrict__ beta,
    float* __restrict__ out)
{
    __shared__ float w1[4], w2[4];
    __shared__ float mu_s, rstd_s;
    const int l = blockIdx.x;
    const int d = threadIdx.x;
    float Rv = 0.f;
    #pragma unroll
    for (int p = 0; p < NRP; p++) Rv += g_Rp[(p * LLEN + l) * DD + d];
    float y = x[l * DD + d] + g_o1[l * DD + d] + blo[d] * Rv;
    float s1 = y, s2 = y * y;
    #pragma unroll
    for (int off = 16; off > 0; off >>= 1) {
        s1 += __shfl_down_sync(0xffffffffu, s1, off);
        s2 += __shfl_down_sync(0xffffffffu, s2, off);
    }
    const int wid = d >> 5, lid = d & 31;
    if (lid == 0) { w1[wid] = s1; w2[wid] = s2; }
    __syncthreads();
    if (d == 0) {
        float t1 = w1[0] + w1[1] + w1[2] + w1[3];
        float t2 = w2[0] + w2[1] + w2[2] + w2[3];
        float mu = t1 * (1.f / DD);
        float var = t2 * (1.f / DD) - mu * mu;
        mu_s = mu; rstd_s = rsqrtf(var + EPSF);
    }
    __syncthreads();
    out[l * DD + d] = (y - mu_s) * rstd_s * gamma[d] + beta[d];
}

// ---------------- launch: two-stream overlap (prep_mask || proj, r || cop) ----------------
extern "C" void kernel_launch(void* const* d_in, const int* in_sizes, int n_in,
                              void* d_out, int out_size)
{
    (void)in_sizes; (void)n_in; (void)out_size;
    const float* x     = (const float*)d_in[0];
    const int*   mask  = (const int*)  d_in[1];
    const float* Wl    = (const float*)d_in[2];
    const float* bl    = (const float*)d_in[3];
    const float* Wlo   = (const float*)d_in[4];
    const float* blo   = (const float*)d_in[5];
    const float* Wl2   = (const float*)d_in[6];
    const float* bl2   = (const float*)d_in[7];
    const float* gamma = (const float*)d_in[8];
    const float* beta  = (const float*)d_in[9];
    float* out = (float*)d_out;

    static cudaStream_t s2 = nullptr;
    static cudaEvent_t evStart, evProj, evMask, evR;
    if (!s2) {
        cudaStreamCreateWithFlags(&s2, cudaStreamNonBlocking);
        cudaEventCreateWithFlags(&evStart, cudaEventDisableTiming);
        cudaEventCreateWithFlags(&evProj,  cudaEventDisableTiming);
        cudaEventCreateWithFlags(&evMask,  cudaEventDisableTiming);
        cudaEventCreateWithFlags(&evR,     cudaEventDisableTiming);
        cudaFuncSetAttribute(cop_kernel, cudaFuncAttributeMaxDynamicSharedMemorySize, 58368);
    }

    // fork side stream off the main (capture) stream
    cudaEventRecord(evStart, 0);
    cudaStreamWaitEvent(s2, evStart, 0);

    // side stream: mask pair-words (independent of proj)
    prep_mask_kernel<<<2048, 256, 0, s2>>>(mask);
    cudaEventRecord(evMask, s2);

    // main stream: projections
    proj_kernel<<<dim3(128, 2), 256>>>(x, Wl, bl, Wl2, bl2);
    cudaEventRecord(evProj, 0);

    // side stream: R partials (needs g_tx from proj; runs concurrent with cop)
    cudaStreamWaitEvent(s2, evProj, 0);
    r_kernel<<<dim3(64, 16), 256, 0, s2>>>(mask);
    cudaEventRecord(evR, s2);

    // main stream: cop (needs proj + masks)
    cudaStreamWaitEvent(0, evMask, 0);
    cop_kernel<<<296, 256, 58368>>>(Wlo);

    // main stream: ln (needs cop + R) — joins side stream back
    cudaStreamWaitEvent(0, evR, 0);
    ln_kernel<<<1024, 128>>>(x, blo, gamma, beta, out);
}